// round 1
// baseline (speedup 1.0000x reference)
#include <cuda_runtime.h>
#include <cuda_bf16.h>
#include <cstdint>

// Problem constants
#define BB   32
#define NN   577
#define CC   768
#define HH   12
#define DD   64
#define MTOK (BB*NN)        // 18464
#define QKVN (3*CC)         // 2304

// Scratch (allocation-free rule: __device__ globals)
__device__ float g_Q[(size_t)BB*HH*NN*DD];
__device__ float g_K[(size_t)BB*HH*NN*DD];
__device__ float g_V[(size_t)BB*HH*NN*DD];
__device__ float g_att[(size_t)MTOK*CC];

// ---------------------------------------------------------------------------
// Shared GEMM mainloop: 128x128 tile, BK=8, 256 threads, 8x8 per thread.
// ---------------------------------------------------------------------------
__device__ __forceinline__ void gemm_main(
    const float* __restrict__ A, const float* __restrict__ W,
    int M, int N, int K, int m0, int n0,
    float (&acc)[8][8], float* __restrict__ xs /*[8][132]*/, float* __restrict__ ws /*[8][128]*/)
{
    const int tid = threadIdx.x;
    const int tx = tid & 15, ty = tid >> 4;
    const int xm  = tid >> 1;         // 0..127 (row within tile)
    const int xk4 = (tid & 1) * 4;    // 0 or 4 (k offset)
    const int wk  = tid >> 5;         // 0..7
    const int wn4 = (tid & 31) * 4;   // 0..124

    for (int k0 = 0; k0 < K; k0 += 8) {
        float4 av = make_float4(0.f, 0.f, 0.f, 0.f);
        int row = m0 + xm;
        if (row < M) av = *(const float4*)(A + (size_t)row * K + k0 + xk4);
        xs[(xk4 + 0) * 132 + xm] = av.x;
        xs[(xk4 + 1) * 132 + xm] = av.y;
        xs[(xk4 + 2) * 132 + xm] = av.z;
        xs[(xk4 + 3) * 132 + xm] = av.w;

        float4 wv = *(const float4*)(W + (size_t)(k0 + wk) * N + n0 + wn4);
        *(float4*)(ws + wk * 128 + wn4) = wv;
        __syncthreads();

        #pragma unroll
        for (int kk = 0; kk < 8; kk++) {
            float a[8], b[8];
            *(float4*)(a)     = *(const float4*)(xs + kk * 132 + ty * 8);
            *(float4*)(a + 4) = *(const float4*)(xs + kk * 132 + ty * 8 + 4);
            *(float4*)(b)     = *(const float4*)(ws + kk * 128 + tx * 8);
            *(float4*)(b + 4) = *(const float4*)(ws + kk * 128 + tx * 8 + 4);
            #pragma unroll
            for (int i = 0; i < 8; i++)
                #pragma unroll
                for (int j = 0; j < 8; j++)
                    acc[i][j] += a[i] * b[j];
        }
        __syncthreads();
    }
}

// ---------------------------------------------------------------------------
// Kernel 1: QKV GEMM + bias + RoPE (non-CLS) + q-scale, scatter to [B,H,N,D].
// Col tile (128 wide, 2304 total) lies entirely in one of q/k/v (768 each).
// RoPE pair (d +/- 32) is on lane tx^4 -> shuffle.
// ---------------------------------------------------------------------------
__global__ void __launch_bounds__(256) qkv_kernel(
    const float* __restrict__ x, const float* __restrict__ w,
    const float* __restrict__ bias,
    const float* __restrict__ rsin, const float* __restrict__ rcos)
{
    __shared__ float xs[8 * 132];
    __shared__ float ws[8 * 128];
    float acc[8][8] = {};
    const int m0 = blockIdx.y * 128;
    const int n0 = blockIdx.x * 128;

    gemm_main(x, w, MTOK, QKVN, CC, m0, n0, acc, xs, ws);

    const int tx = threadIdx.x & 15, ty = threadIdx.x >> 4;
    const int which = n0 / CC;            // 0=q,1=k,2=v (uniform per block)
    float* dst = (which == 0) ? g_Q : ((which == 1) ? g_K : g_V);
    const bool is_v = (which == 2);
    const bool is_q = (which == 0);

    #pragma unroll
    for (int i = 0; i < 8; i++) {
        int r = m0 + ty * 8 + i;
        bool valid = (r < MTOK);
        int rr = valid ? r : 0;
        int bb = rr / NN;
        int n  = rr - bb * NN;
        #pragma unroll
        for (int j = 0; j < 8; j++) {
            int c = n0 + tx * 8 + j;
            float v = acc[i][j] + bias[c];
            // Pair value for rotate_half: lane tx^4, same j. Bias already added per-lane.
            float pv = __shfl_xor_sync(0xffffffffu, v, 4);
            float outv = v;
            int d = (tx * 8 + j) & 63;
            if (!is_v && n > 0 && valid) {
                float cs = rcos[(n - 1) * DD + d];
                float sn = rsin[(n - 1) * DD + d];
                float rot = (tx & 4) ? pv : -pv;  // d<32: -t[d+32] ; d>=32: +t[d-32]
                outv = v * cs + rot * sn;
            }
            if (is_q) outv *= 0.125f;             // 1/sqrt(64), applied to all tokens
            if (valid) {
                int cc = c - which * CC;
                int h = cc >> 6;
                dst[(((size_t)bb * HH + h) * NN + n) * DD + d] = outv;
            }
        }
    }
}

// ---------------------------------------------------------------------------
// Kernel 2: flash attention. Block = (b, h, 64-row q-tile). 256 threads,
// 4x4 per thread for S (64x64) and O (64x64). Online softmax with m/l in regs.
// Dynamic smem: Qs[64*64] + Ks[64*65] (reused as P) + Vs[64*65].
// ---------------------------------------------------------------------------
#define ATTN_SMEM_FLOATS (64*64 + 64*65 + 64*65)
#define ATTN_SMEM_BYTES  (ATTN_SMEM_FLOATS * 4)

__global__ void __launch_bounds__(256) attn_kernel()
{
    extern __shared__ float sm[];
    float* Qs = sm;               // [64][64]
    float* Ks = Qs + 64 * 64;     // [64][65], becomes P after S computed
    float* Vs = Ks + 64 * 65;     // [64][65]

    const int tid = threadIdx.x;
    const int tx = tid & 15, ty = tid >> 4;
    const int q0 = blockIdx.x * 64;
    const int bh = blockIdx.y;                 // b*12 + h
    const int b = bh / HH, h = bh - b * HH;

    const float* Qp = g_Q + (size_t)bh * NN * DD;
    const float* Kp = g_K + (size_t)bh * NN * DD;
    const float* Vp = g_V + (size_t)bh * NN * DD;

    // Load Q tile (zero-pad out-of-range q rows)
    #pragma unroll
    for (int t = 0; t < 16; t++) {
        int idx = tid + t * 256;
        int r = idx >> 6, d = idx & 63;
        int qn = q0 + r;
        Qs[r * 64 + d] = (qn < NN) ? Qp[(size_t)qn * DD + d] : 0.f;
    }

    float o[4][4] = {};
    float m_st[4], l_st[4];
    #pragma unroll
    for (int i = 0; i < 4; i++) { m_st[i] = -1e30f; l_st[i] = 0.f; }
    __syncthreads();

    const int NKT = (NN + 63) / 64;   // 10
    for (int kt = 0; kt < NKT; kt++) {
        int kb = kt * 64;
        // Load K, V tiles (zero-pad)
        #pragma unroll
        for (int t = 0; t < 16; t++) {
            int idx = tid + t * 256;
            int r = idx >> 6, d = idx & 63;
            int kn = kb + r;
            bool valid = (kn < NN);
            Ks[r * 65 + d] = valid ? Kp[(size_t)kn * DD + d] : 0.f;
            Vs[r * 65 + d] = valid ? Vp[(size_t)kn * DD + d] : 0.f;
        }
        __syncthreads();

        // S = Q K^T (4x4 per thread)
        float s[4][4] = {};
        #pragma unroll 4
        for (int d = 0; d < 64; d++) {
            float qa[4], kbv[4];
            #pragma unroll
            for (int i = 0; i < 4; i++) qa[i]  = Qs[(ty * 4 + i) * 64 + d];
            #pragma unroll
            for (int j = 0; j < 4; j++) kbv[j] = Ks[(tx * 4 + j) * 65 + d];
            #pragma unroll
            for (int i = 0; i < 4; i++)
                #pragma unroll
                for (int j = 0; j < 4; j++)
                    s[i][j] += qa[i] * kbv[j];
        }
        // Mask invalid keys
        #pragma unroll
        for (int j = 0; j < 4; j++)
            if (kb + tx * 4 + j >= NN)
                #pragma unroll
                for (int i = 0; i < 4; i++) s[i][j] = -1e30f;

        // Online softmax: row max / sum via shfl butterfly over tx (bits 1,2,4,8)
        float p[4][4];
        float rowsum[4];
        #pragma unroll
        for (int i = 0; i < 4; i++) {
            float rm = s[i][0];
            #pragma unroll
            for (int j = 1; j < 4; j++) rm = fmaxf(rm, s[i][j]);
            #pragma unroll
            for (int off = 8; off >= 1; off >>= 1)
                rm = fmaxf(rm, __shfl_xor_sync(0xffffffffu, rm, off));
            float m_new = fmaxf(m_st[i], rm);
            float scale = __expf(m_st[i] - m_new);
            float rs = 0.f;
            #pragma unroll
            for (int j = 0; j < 4; j++) {
                p[i][j] = __expf(s[i][j] - m_new);
                rs += p[i][j];
            }
            #pragma unroll
            for (int off = 8; off >= 1; off >>= 1)
                rs += __shfl_xor_sync(0xffffffffu, rs, off);
            rowsum[i] = rs;
            m_st[i] = m_new;
            l_st[i] = l_st[i] * scale + rs;
            #pragma unroll
            for (int jo = 0; jo < 4; jo++) o[i][jo] *= scale;
        }

        __syncthreads();   // everyone done reading Ks -> safe to overwrite with P
        #pragma unroll
        for (int i = 0; i < 4; i++)
            #pragma unroll
            for (int j = 0; j < 4; j++)
                Ks[(ty * 4 + i) * 65 + (tx * 4 + j)] = p[i][j];
        __syncthreads();

        // O += P @ V
        #pragma unroll 4
        for (int k = 0; k < 64; k++) {
            float pa[4], vb[4];
            #pragma unroll
            for (int i = 0; i < 4; i++)  pa[i] = Ks[(ty * 4 + i) * 65 + k];
            #pragma unroll
            for (int jo = 0; jo < 4; jo++) vb[jo] = Vs[k * 65 + tx * 4 + jo];
            #pragma unroll
            for (int i = 0; i < 4; i++)
                #pragma unroll
                for (int jo = 0; jo < 4; jo++)
                    o[i][jo] += pa[i] * vb[jo];
        }
        __syncthreads();   // before next tile overwrites Ks/Vs
        (void)rowsum;
    }

    // Epilogue: O / l -> g_att[B, N, C] with C index h*64+d
    #pragma unroll
    for (int i = 0; i < 4; i++) {
        int n = q0 + ty * 4 + i;
        if (n >= NN) continue;
        float inv_l = 1.0f / l_st[i];
        #pragma unroll
        for (int jo = 0; jo < 4; jo++) {
            int d = tx * 4 + jo;
            g_att[((size_t)b * NN + n) * CC + h * DD + d] = o[i][jo] * inv_l;
        }
    }
}

// ---------------------------------------------------------------------------
// Kernel 3: output projection: g_att[18464,768] @ w_proj[768,768] + b_proj
// ---------------------------------------------------------------------------
__global__ void __launch_bounds__(256) proj_kernel(
    const float* __restrict__ w, const float* __restrict__ bias,
    float* __restrict__ out)
{
    __shared__ float xs[8 * 132];
    __shared__ float ws[8 * 128];
    float acc[8][8] = {};
    const int m0 = blockIdx.y * 128;
    const int n0 = blockIdx.x * 128;

    gemm_main(g_att, w, MTOK, CC, CC, m0, n0, acc, xs, ws);

    const int tx = threadIdx.x & 15, ty = threadIdx.x >> 4;
    #pragma unroll
    for (int i = 0; i < 8; i++) {
        int r = m0 + ty * 8 + i;
        if (r >= MTOK) continue;
        #pragma unroll
        for (int j = 0; j < 8; j++) {
            int c = n0 + tx * 8 + j;
            out[(size_t)r * CC + c] = acc[i][j] + bias[c];
        }
    }
}

// ---------------------------------------------------------------------------
extern "C" void kernel_launch(void* const* d_in, const int* in_sizes, int n_in,
                              void* d_out, int out_size)
{
    (void)in_sizes; (void)n_in; (void)out_size;
    const float* x      = (const float*)d_in[0];
    const float* w_qkv  = (const float*)d_in[1];
    const float* b_qkv  = (const float*)d_in[2];
    const float* w_proj = (const float*)d_in[3];
    const float* b_proj = (const float*)d_in[4];
    const float* rsin   = (const float*)d_in[5];
    const float* rcos   = (const float*)d_in[6];
    float* out = (float*)d_out;

    // >48KB dynamic smem opt-in (idempotent, not a stream op; capture-safe)
    cudaFuncSetAttribute(attn_kernel, cudaFuncAttributeMaxDynamicSharedMemorySize,
                         ATTN_SMEM_BYTES);

    dim3 g1(QKVN / 128, (MTOK + 127) / 128);     // 18 x 145
    qkv_kernel<<<g1, 256>>>(x, w_qkv, b_qkv, rsin, rcos);

    dim3 g2((NN + 63) / 64, BB * HH);            // 10 x 384
    attn_kernel<<<g2, 256, ATTN_SMEM_BYTES>>>();

    dim3 g3(CC / 128, (MTOK + 127) / 128);       // 6 x 145
    proj_kernel<<<g3, 256>>>(w_proj, b_proj, out);
}

// round 2
// speedup vs baseline: 3.2043x; 3.2043x over previous
#include <cuda_runtime.h>
#include <cuda_bf16.h>
#include <cstdint>

#define BB   32
#define NN   577
#define CC   768
#define HH   12
#define DD   64
#define MTOK (BB*NN)        // 18464
#define QKVN (3*CC)         // 2304

// Scratch (allocation-free rule: __device__ globals)
__device__ float g_Q[(size_t)BB*HH*NN*DD];
__device__ float g_K[(size_t)BB*HH*NN*DD];
__device__ float g_V[(size_t)BB*HH*NN*DD];
__device__ float g_att[(size_t)MTOK*CC];

// ---------------------------------------------------------------------------
// tf32 helpers
// ---------------------------------------------------------------------------
__device__ __forceinline__ uint32_t f2tf32(float x) {
    uint32_t r; asm("cvt.rna.tf32.f32 %0, %1;" : "=r"(r) : "f"(x)); return r;
}
__device__ __forceinline__ float tf32f(float x) {
    uint32_t r; asm("cvt.rna.tf32.f32 %0, %1;" : "=r"(r) : "f"(x));
    return __uint_as_float(r);
}
__device__ __forceinline__ void mma_tf32(float (&d)[4], const uint32_t (&a)[4],
                                         const uint32_t b0, const uint32_t b1,
                                         const float (&c)[4]) {
    asm volatile(
        "mma.sync.aligned.m16n8k8.row.col.f32.tf32.tf32.f32 "
        "{%0,%1,%2,%3}, {%4,%5,%6,%7}, {%8,%9}, {%10,%11,%12,%13};\n"
        : "=f"(d[0]), "=f"(d[1]), "=f"(d[2]), "=f"(d[3])
        : "r"(a[0]), "r"(a[1]), "r"(a[2]), "r"(a[3]),
          "r"(b0), "r"(b1),
          "f"(c[0]), "f"(c[1]), "f"(c[2]), "f"(c[3]));
}

// ---------------------------------------------------------------------------
// Tensor-core GEMM mainloop: 128(M) x 128(N) tile, BK=16, 256 thr (8 warps).
// Warp layout: warp_m = wid&3 (32 rows = 2 m-frags), warp_n = wid>>2 (64 cols
// = 8 n-frags). Double-buffered SMEM; tf32 conversion at SMEM-store time.
// As stride 20 (m-major [128][16+4]); Bs stride 136 (k-major [16][128+8]).
// ---------------------------------------------------------------------------
#define AS_STR 20
#define BS_STR 136
#define AS_SZ  (128*AS_STR)
#define BS_SZ  (16*BS_STR)

__device__ __forceinline__ void gemm_tc(
    const float* __restrict__ A, const float* __restrict__ W,
    int M, int Kdim, int Nld, int m0, int n0,
    float (&acc)[2][8][4], float* __restrict__ As, float* __restrict__ Bs)
{
    const int tid  = threadIdx.x;
    const int lane = tid & 31;
    const int wid  = tid >> 5;
    const int grp  = lane >> 2;
    const int tid4 = lane & 3;
    const int wm32 = (wid & 3) * 32;
    const int wn64 = (wid >> 2) * 64;

    // GMEM staging indices
    const int ar0 = tid >> 2,  ac4 = (tid & 3) * 4;      // A: (row, kcol) pairs
    const int bk0 = tid >> 5,  bc4 = (tid & 31) * 4;     // B: (krow, ncol)

    float4 ra[2], rb[2];
    const int KT = Kdim / 16;

    auto load_regs = [&](int t) {
        int k0 = t * 16;
        #pragma unroll
        for (int i = 0; i < 2; i++) {
            int row = ar0 + i * 64;
            int gr = m0 + row;
            ra[i] = (gr < M) ? *(const float4*)(A + (size_t)gr * Kdim + k0 + ac4)
                             : make_float4(0.f, 0.f, 0.f, 0.f);
            int kr = bk0 + i * 8;
            rb[i] = *(const float4*)(W + (size_t)(k0 + kr) * Nld + n0 + bc4);
        }
    };
    auto store_smem = [&](int buf) {
        float* as = As + buf * AS_SZ;
        float* bs = Bs + buf * BS_SZ;
        #pragma unroll
        for (int i = 0; i < 2; i++) {
            int row = ar0 + i * 64;
            float4 v = ra[i];
            v.x = tf32f(v.x); v.y = tf32f(v.y); v.z = tf32f(v.z); v.w = tf32f(v.w);
            *(float4*)(as + row * AS_STR + ac4) = v;
            int kr = bk0 + i * 8;
            float4 w4 = rb[i];
            w4.x = tf32f(w4.x); w4.y = tf32f(w4.y); w4.z = tf32f(w4.z); w4.w = tf32f(w4.w);
            *(float4*)(bs + kr * BS_STR + bc4) = w4;
        }
    };

    load_regs(0);
    store_smem(0);
    __syncthreads();

    for (int t = 0; t < KT; t++) {
        if (t + 1 < KT) load_regs(t + 1);

        const float* as = As + (t & 1) * AS_SZ;
        const float* bs = Bs + (t & 1) * BS_SZ;
        #pragma unroll
        for (int ks = 0; ks < 16; ks += 8) {
            uint32_t a[2][4];
            #pragma unroll
            for (int mt = 0; mt < 2; mt++) {
                int r = wm32 + mt * 16 + grp;
                a[mt][0] = __float_as_uint(as[r * AS_STR + ks + tid4]);
                a[mt][1] = __float_as_uint(as[(r + 8) * AS_STR + ks + tid4]);
                a[mt][2] = __float_as_uint(as[r * AS_STR + ks + tid4 + 4]);
                a[mt][3] = __float_as_uint(as[(r + 8) * AS_STR + ks + tid4 + 4]);
            }
            #pragma unroll
            for (int nt = 0; nt < 8; nt++) {
                int c = wn64 + nt * 8 + grp;
                uint32_t b0 = __float_as_uint(bs[(ks + tid4) * BS_STR + c]);
                uint32_t b1 = __float_as_uint(bs[(ks + tid4 + 4) * BS_STR + c]);
                #pragma unroll
                for (int mt = 0; mt < 2; mt++)
                    mma_tf32(acc[mt][nt], a[mt], b0, b1, acc[mt][nt]);
            }
        }
        __syncthreads();
        if (t + 1 < KT) {
            store_smem((t + 1) & 1);
            __syncthreads();
        }
    }
}

// ---------------------------------------------------------------------------
// Kernel 1: QKV GEMM + bias + RoPE + q-scale, scatter to [B,H,N,D].
// Each warp's 64-col span is exactly one head: the RoPE pair (d, d^32) lives
// in the same thread at n-tile nt^4, same register index.
// ---------------------------------------------------------------------------
__global__ void __launch_bounds__(256) qkv_kernel(
    const float* __restrict__ x, const float* __restrict__ w,
    const float* __restrict__ bias,
    const float* __restrict__ rsin, const float* __restrict__ rcos)
{
    __shared__ float As[2 * AS_SZ];
    __shared__ float Bs[2 * BS_SZ];
    float acc[2][8][4] = {};

    const int m0 = blockIdx.y * 128;
    const int n0 = blockIdx.x * 128;

    gemm_tc(x, w, MTOK, CC, QKVN, m0, n0, acc, As, Bs);

    const int lane = threadIdx.x & 31;
    const int wid  = threadIdx.x >> 5;
    const int grp  = lane >> 2;
    const int tid4 = lane & 3;
    const int wm32 = (wid & 3) * 32;
    const int wn64 = (wid >> 2) * 64;

    const int which = n0 / CC;                       // 0=q,1=k,2=v
    float* dst = (which == 0) ? g_Q : ((which == 1) ? g_K : g_V);
    const int h = ((n0 + wn64) % CC) / DD;
    const bool is_v = (which == 2);
    const bool is_q = (which == 0);

    // pass 1: add bias in place
    #pragma unroll
    for (int nt = 0; nt < 8; nt++) {
        int c = n0 + wn64 + nt * 8 + 2 * tid4;
        float b0 = bias[c], b1 = bias[c + 1];
        #pragma unroll
        for (int mt = 0; mt < 2; mt++) {
            acc[mt][nt][0] += b0; acc[mt][nt][1] += b1;
            acc[mt][nt][2] += b0; acc[mt][nt][3] += b1;
        }
    }

    // pass 2: RoPE + scale + scatter (reads acc, never writes it)
    #pragma unroll
    for (int mt = 0; mt < 2; mt++) {
        #pragma unroll
        for (int rr = 0; rr < 2; rr++) {
            int m = m0 + wm32 + mt * 16 + grp + rr * 8;
            if (m >= MTOK) continue;
            int bb = m / NN;
            int n  = m - bb * NN;
            #pragma unroll
            for (int nt = 0; nt < 8; nt++) {
                int d0 = nt * 8 + 2 * tid4;
                float v0 = acc[mt][nt][2 * rr];
                float v1 = acc[mt][nt][2 * rr + 1];
                float o0 = v0, o1 = v1;
                if (!is_v && n > 0) {
                    float p0 = acc[mt][nt ^ 4][2 * rr];
                    float p1 = acc[mt][nt ^ 4][2 * rr + 1];
                    float sgn = (nt < 4) ? -1.f : 1.f;
                    float c0 = rcos[(n - 1) * DD + d0],     s0 = rsin[(n - 1) * DD + d0];
                    float c1 = rcos[(n - 1) * DD + d0 + 1], s1 = rsin[(n - 1) * DD + d0 + 1];
                    o0 = v0 * c0 + sgn * p0 * s0;
                    o1 = v1 * c1 + sgn * p1 * s1;
                }
                if (is_q) { o0 *= 0.125f; o1 *= 0.125f; }
                float2 ov = make_float2(o0, o1);
                *(float2*)(dst + (((size_t)bb * HH + h) * NN + n) * DD + d0) = ov;
            }
        }
    }
}

// ---------------------------------------------------------------------------
// Kernel 2: flash attention, tensor cores.
// Block = (128-row q-tile, b*h). 8 warps, warp = 16 q-rows x all 64 cols.
// Q fragments register-resident. K-tiles of 64 rows. P via per-warp SMEM strip.
// ---------------------------------------------------------------------------
#define KS_STR 68
#define VS_STR 72
#define PS_STR 68
#define SM_KS  0
#define SM_VS  (64*KS_STR)              // 4352
#define SM_PS  (SM_VS + 64*VS_STR)      // 8960
#define ATTN_SMEM_FLOATS (SM_PS + 128*PS_STR)
#define ATTN_SMEM_BYTES  (ATTN_SMEM_FLOATS*4)   // 70656

__global__ void __launch_bounds__(256) attn_kernel()
{
    extern __shared__ float sm[];
    float* Ks = sm + SM_KS;
    float* Vs = sm + SM_VS;
    float* Ps = sm + SM_PS;

    const int tid  = threadIdx.x;
    const int lane = tid & 31;
    const int wid  = tid >> 5;
    const int grp  = lane >> 2;
    const int tid4 = lane & 3;

    const int q0 = blockIdx.x * 128;
    const int bh = blockIdx.y;
    const int b = bh / HH, h = bh - b * HH;

    const float* Qp = g_Q + (size_t)bh * NN * DD;
    const float* Kp = g_K + (size_t)bh * NN * DD;
    const float* Vp = g_V + (size_t)bh * NN * DD;

    // Stage Q tile (128x64) into Ps, zero-padded
    #pragma unroll
    for (int i = 0; i < 8; i++) {
        int pos = i * 256 + tid;           // 2048 float4 slots
        int r = pos >> 4, c4 = (pos & 15) * 4;
        float4 v = make_float4(0.f, 0.f, 0.f, 0.f);
        if (q0 + r < NN) v = *(const float4*)(Qp + (size_t)(q0 + r) * DD + c4);
        *(float4*)(Ps + r * PS_STR + c4) = v;
    }
    __syncthreads();

    // Q fragments (register resident, tf32)
    uint32_t aq[8][4];
    {
        const float* qs = Ps + (wid * 16 + grp) * PS_STR;
        #pragma unroll
        for (int ks = 0; ks < 8; ks++) {
            aq[ks][0] = f2tf32(qs[ks * 8 + tid4]);
            aq[ks][1] = f2tf32(qs[8 * PS_STR + ks * 8 + tid4]);
            aq[ks][2] = f2tf32(qs[ks * 8 + tid4 + 4]);
            aq[ks][3] = f2tf32(qs[8 * PS_STR + ks * 8 + tid4 + 4]);
        }
    }
    // No block sync needed: each warp only reads/writes its own Ps strip below.

    float o[8][4] = {};
    float m_st[2] = {-1e30f, -1e30f};
    float l_st[2] = {0.f, 0.f};

    const int NKT = (NN + 63) / 64;   // 10
    for (int kt = 0; kt < NKT; kt++) {
        int kb = kt * 64;
        __syncthreads();   // prior iteration's reads of Ks/Vs complete
        #pragma unroll
        for (int i = 0; i < 4; i++) {
            int pos = i * 256 + tid;       // 1024 float4 per matrix
            int r = pos >> 4, c4 = (pos & 15) * 4;
            bool valid = (kb + r < NN);
            float4 kv = valid ? *(const float4*)(Kp + (size_t)(kb + r) * DD + c4)
                              : make_float4(0.f, 0.f, 0.f, 0.f);
            float4 vv = valid ? *(const float4*)(Vp + (size_t)(kb + r) * DD + c4)
                              : make_float4(0.f, 0.f, 0.f, 0.f);
            kv.x = tf32f(kv.x); kv.y = tf32f(kv.y); kv.z = tf32f(kv.z); kv.w = tf32f(kv.w);
            vv.x = tf32f(vv.x); vv.y = tf32f(vv.y); vv.z = tf32f(vv.z); vv.w = tf32f(vv.w);
            *(float4*)(Ks + r * KS_STR + c4) = kv;
            *(float4*)(Vs + r * VS_STR + c4) = vv;
        }
        __syncthreads();

        // S = Q K^T : per-warp 16x64 strip, frags s[8][4]
        float s[8][4] = {};
        #pragma unroll
        for (int ks = 0; ks < 8; ks++) {
            #pragma unroll
            for (int nt = 0; nt < 8; nt++) {
                const float* kr = Ks + (nt * 8 + grp) * KS_STR + ks * 8 + tid4;
                uint32_t b0 = __float_as_uint(kr[0]);
                uint32_t b1 = __float_as_uint(kr[4]);
                mma_tf32(s[nt], aq[ks], b0, b1, s[nt]);
            }
        }

        // Mask invalid key columns (only last tile)
        if (kb + 64 > NN) {
            #pragma unroll
            for (int nt = 0; nt < 8; nt++) {
                int c = kb + nt * 8 + 2 * tid4;
                if (c >= NN)     { s[nt][0] = -1e30f; s[nt][2] = -1e30f; }
                if (c + 1 >= NN) { s[nt][1] = -1e30f; s[nt][3] = -1e30f; }
            }
        }

        // Online softmax, rows grp (rr=0) and grp+8 (rr=1)
        #pragma unroll
        for (int rr = 0; rr < 2; rr++) {
            float rm = -1e30f;
            #pragma unroll
            for (int nt = 0; nt < 8; nt++)
                rm = fmaxf(rm, fmaxf(s[nt][2 * rr], s[nt][2 * rr + 1]));
            rm = fmaxf(rm, __shfl_xor_sync(0xffffffffu, rm, 1));
            rm = fmaxf(rm, __shfl_xor_sync(0xffffffffu, rm, 2));
            float m_new = fmaxf(m_st[rr], rm);
            float scale = __expf(m_st[rr] - m_new);
            float rs = 0.f;
            #pragma unroll
            for (int nt = 0; nt < 8; nt++) {
                float p0 = tf32f(__expf(s[nt][2 * rr]     - m_new));
                float p1 = tf32f(__expf(s[nt][2 * rr + 1] - m_new));
                s[nt][2 * rr] = p0; s[nt][2 * rr + 1] = p1;
                rs += p0 + p1;
            }
            rs += __shfl_xor_sync(0xffffffffu, rs, 1);
            rs += __shfl_xor_sync(0xffffffffu, rs, 2);
            m_st[rr] = m_new;
            l_st[rr] = l_st[rr] * scale + rs;
            #pragma unroll
            for (int nt = 0; nt < 8; nt++) {
                o[nt][2 * rr] *= scale; o[nt][2 * rr + 1] *= scale;
            }
        }

        // P -> per-warp private SMEM strip (tf32 bits already)
        {
            float* ps = Ps + (wid * 16 + grp) * PS_STR;
            #pragma unroll
            for (int nt = 0; nt < 8; nt++) {
                *(float2*)(ps + nt * 8 + 2 * tid4) = make_float2(s[nt][0], s[nt][1]);
                *(float2*)(ps + 8 * PS_STR + nt * 8 + 2 * tid4) = make_float2(s[nt][2], s[nt][3]);
            }
        }
        __syncwarp();

        // O += P @ V
        {
            const float* ps = Ps + (wid * 16 + grp) * PS_STR;
            #pragma unroll
            for (int ks = 0; ks < 8; ks++) {
                uint32_t ap[4];
                ap[0] = __float_as_uint(ps[ks * 8 + tid4]);
                ap[1] = __float_as_uint(ps[8 * PS_STR + ks * 8 + tid4]);
                ap[2] = __float_as_uint(ps[ks * 8 + tid4 + 4]);
                ap[3] = __float_as_uint(ps[8 * PS_STR + ks * 8 + tid4 + 4]);
                #pragma unroll
                for (int nt = 0; nt < 8; nt++) {
                    const float* vr = Vs + (ks * 8 + tid4) * VS_STR + nt * 8 + grp;
                    uint32_t b0 = __float_as_uint(vr[0]);
                    uint32_t b1 = __float_as_uint(vr[4 * VS_STR]);
                    mma_tf32(o[nt], ap, b0, b1, o[nt]);
                }
            }
        }
        __syncwarp();
    }

    // Epilogue: O / l -> g_att[B, N, C]
    #pragma unroll
    for (int rr = 0; rr < 2; rr++) {
        int n = q0 + wid * 16 + grp + rr * 8;
        if (n >= NN) continue;
        float inv_l = 1.0f / l_st[rr];
        #pragma unroll
        for (int nt = 0; nt < 8; nt++) {
            int d0 = nt * 8 + 2 * tid4;
            float2 ov = make_float2(o[nt][2 * rr] * inv_l, o[nt][2 * rr + 1] * inv_l);
            *(float2*)(g_att + ((size_t)b * NN + n) * CC + h * DD + d0) = ov;
        }
    }
}

// ---------------------------------------------------------------------------
// Kernel 3: output projection + bias -> d_out
// ---------------------------------------------------------------------------
__global__ void __launch_bounds__(256) proj_kernel(
    const float* __restrict__ w, const float* __restrict__ bias,
    float* __restrict__ out)
{
    __shared__ float As[2 * AS_SZ];
    __shared__ float Bs[2 * BS_SZ];
    float acc[2][8][4] = {};

    const int m0 = blockIdx.y * 128;
    const int n0 = blockIdx.x * 128;

    gemm_tc(g_att, w, MTOK, CC, CC, m0, n0, acc, As, Bs);

    const int lane = threadIdx.x & 31;
    const int wid  = threadIdx.x >> 5;
    const int grp  = lane >> 2;
    const int tid4 = lane & 3;
    const int wm32 = (wid & 3) * 32;
    const int wn64 = (wid >> 2) * 64;

    #pragma unroll
    for (int mt = 0; mt < 2; mt++) {
        #pragma unroll
        for (int rr = 0; rr < 2; rr++) {
            int r = m0 + wm32 + mt * 16 + grp + rr * 8;
            if (r >= MTOK) continue;
            #pragma unroll
            for (int nt = 0; nt < 8; nt++) {
                int c = n0 + wn64 + nt * 8 + 2 * tid4;
                float2 ov = make_float2(acc[mt][nt][2 * rr] + bias[c],
                                        acc[mt][nt][2 * rr + 1] + bias[c + 1]);
                *(float2*)(out + (size_t)r * CC + c) = ov;
            }
        }
    }
}

// ---------------------------------------------------------------------------
extern "C" void kernel_launch(void* const* d_in, const int* in_sizes, int n_in,
                              void* d_out, int out_size)
{
    (void)in_sizes; (void)n_in; (void)out_size;
    const float* x      = (const float*)d_in[0];
    const float* w_qkv  = (const float*)d_in[1];
    const float* b_qkv  = (const float*)d_in[2];
    const float* w_proj = (const float*)d_in[3];
    const float* b_proj = (const float*)d_in[4];
    const float* rsin   = (const float*)d_in[5];
    const float* rcos   = (const float*)d_in[6];
    float* out = (float*)d_out;

    cudaFuncSetAttribute(attn_kernel, cudaFuncAttributeMaxDynamicSharedMemorySize,
                         ATTN_SMEM_BYTES);

    dim3 g1(QKVN / 128, (MTOK + 127) / 128);     // 18 x 145
    qkv_kernel<<<g1, 256>>>(x, w_qkv, b_qkv, rsin, rcos);

    dim3 g2((NN + 127) / 128, BB * HH);          // 5 x 384
    attn_kernel<<<g2, 256, ATTN_SMEM_BYTES>>>();

    dim3 g3(CC / 128, (MTOK + 127) / 128);       // 6 x 145
    proj_kernel<<<g3, 256>>>(w_proj, b_proj, out);
}